// round 16
// baseline (speedup 1.0000x reference)
#include <cuda_runtime.h>
#include <cstdint>

// DecisionGate: g = 1/(1+|x|^4); mask = g>=0.5; dispatched[b,p,:] = (mask? g:0)*act[b,:]
// x [4096,64] f32, act [4096,512] f32. Output f32: g [B*P] | mask [B*P] | dispatched [B*P*D]
//
// R16: TMA bulk-store path (R15 showed best DRAM%/ncu-dur of series at only
// 31% occ), re-tuned for occupancy: 4-row/8KB chunks, 2 buffers = 16KB smem
// (vs 33KB) -> ~13 CTAs/SM. Double-buffered fill/drain, <=2 bulk groups in
// flight per CTA.

#define B_DIM 4096
#define P_DIM 64
#define D_DIM 512
#define BP    (B_DIM * P_DIM)
#define CHUNK 4                            // p-rows per bulk store
#define CHUNK_F4 (CHUNK * D_DIM / 4)       // 512 float4 = 8KB
#define N_CHUNKS (P_DIM / CHUNK)           // 16

__device__ __forceinline__ uint32_t smem_u32(const void* p) {
    return (uint32_t)__cvta_generic_to_shared(p);
}

__global__ __launch_bounds__(128, 12)
void decision_gate_kernel(const float* __restrict__ x,
                          const float* __restrict__ act,
                          float* __restrict__ out) {
    const int b = blockIdx.x;
    const int t = threadIdx.x;             // 0..127, one float4 of D=512 each

    __shared__ alignas(128) float4 buf[2][CHUNK_F4];
    __shared__ float wsm[P_DIM];

    // Each thread owns one float4 of act[b].
    const float4 v = reinterpret_cast<const float4*>(act + (size_t)b * D_DIM)[t];

    if (t < P_DIM) {
        const float xv = x[b * P_DIM + t];
        const float x2 = xv * xv;
        const float g  = 1.0f / (1.0f + x2 * x2);
        const bool  m  = (g >= 0.5f);
        __stcs(&out[b * P_DIM + t], g);
        __stcs(&out[BP + b * P_DIM + t], m ? 1.0f : 0.0f);
        wsm[t] = m ? g : 0.0f;
    }
    __syncthreads();

    float* __restrict__ gdst =
        out + (size_t)2 * BP + (size_t)b * P_DIM * D_DIM;

    #pragma unroll
    for (int c = 0; c < N_CHUNKS; c++) {
        const int cb = c & 1;

        // Recycle buffer cb: the group issued 2 chunks ago (which read this
        // buffer) must have completed. wait_group 1 -> at most 1 still pending.
        if (c >= 2) {
            if (t == 0)
                asm volatile("cp.async.bulk.wait_group 1;" ::: "memory");
            __syncthreads();
        }

        // Fill 4 rows: thread t writes float4 slot t of each row.
        #pragma unroll
        for (int r = 0; r < CHUNK; r++) {
            const float w = wsm[c * CHUNK + r];
            float4 o;
            o.x = v.x * w; o.y = v.y * w; o.z = v.z * w; o.w = v.w * w;
            buf[cb][r * (D_DIM / 4) + t] = o;
        }
        // Make generic-proxy STS visible to the async proxy, then hand off.
        asm volatile("fence.proxy.async.shared::cta;" ::: "memory");
        __syncthreads();

        if (t == 0) {
            asm volatile(
                "cp.async.bulk.global.shared::cta.bulk_group [%0], [%1], %2;"
                :: "l"(gdst + (size_t)c * CHUNK * D_DIM),
                   "r"(smem_u32(&buf[cb][0])),
                   "n"(CHUNK * D_DIM * 4)
                : "memory");
            asm volatile("cp.async.bulk.commit_group;" ::: "memory");
        }
    }

    // Drain before CTA exit.
    if (t == 0)
        asm volatile("cp.async.bulk.wait_group 0;" ::: "memory");
}

extern "C" void kernel_launch(void* const* d_in, const int* in_sizes, int n_in,
                              void* d_out, int out_size) {
    const float* x   = (const float*)d_in[0];   // [4096, 64]
    const float* act = (const float*)d_in[1];   // [4096, 512]
    float* out = (float*)d_out;

    decision_gate_kernel<<<B_DIM, 128>>>(x, act, out);
}

// round 17
// speedup vs baseline: 1.0088x; 1.0088x over previous
#include <cuda_runtime.h>
#include <cstdint>

// DecisionGate: g = 1/(1+|x|^4); mask = g>=0.5; dispatched[b,p,:] = (mask? g:0)*act[b,:]
// x [4096,64] f32, act [4096,512] f32. Output f32: g [B*P] | mask [B*P] | dispatched [B*P*D]
//
// R17 hybrid: drive BOTH store-in paths concurrently. Rows 0..31 via
// per-thread STG.cs from registers (R7 path); rows 32..63 via 4x16KB TMA
// bulk stores (R15's best chunk size). STG bursts are issued between TMA
// chunk handoffs so warps work while the TMA engine drains.

#define B_DIM 4096
#define P_DIM 64
#define D_DIM 512
#define BP    (B_DIM * P_DIM)
#define CHUNK 8                            // p-rows per bulk store (16KB)
#define CHUNK_F4 (CHUNK * D_DIM / 4)       // 1024 float4
#define TMA_BASE 32                        // rows 32..63 via TMA
#define N_CHUNKS ((P_DIM - TMA_BASE) / CHUNK)  // 4

__device__ __forceinline__ uint32_t smem_u32(const void* p) {
    return (uint32_t)__cvta_generic_to_shared(p);
}

__global__ __launch_bounds__(128, 7)
void decision_gate_kernel(const float* __restrict__ x,
                          const float* __restrict__ act,
                          float* __restrict__ out) {
    const int b = blockIdx.x;
    const int t = threadIdx.x;             // 0..127, one float4 of D=512 each

    __shared__ alignas(128) float4 buf[2][CHUNK_F4];   // 2 x 16KB
    __shared__ float wsm[P_DIM];

    // Each thread owns one float4 of act[b].
    const float4 v = reinterpret_cast<const float4*>(act + (size_t)b * D_DIM)[t];

    if (t < P_DIM) {
        const float xv = x[b * P_DIM + t];
        const float x2 = xv * xv;
        const float g  = 1.0f / (1.0f + x2 * x2);
        const bool  m  = (g >= 0.5f);
        __stcs(&out[b * P_DIM + t], g);
        __stcs(&out[BP + b * P_DIM + t], m ? 1.0f : 0.0f);
        wsm[t] = m ? g : 0.0f;
    }
    __syncthreads();

    float* __restrict__ grow =
        out + (size_t)2 * BP + (size_t)b * P_DIM * D_DIM;
    float4* __restrict__ sbase = reinterpret_cast<float4*>(grow) + t;

    #pragma unroll
    for (int c = 0; c < N_CHUNKS; c++) {
        const int cb = c & 1;

        // Recycle buffer cb (group issued 2 chunks ago must be done).
        if (c >= 2) {
            if (t == 0)
                asm volatile("cp.async.bulk.wait_group 1;" ::: "memory");
            __syncthreads();
        }

        // Fill 8 TMA rows into smem.
        #pragma unroll
        for (int r = 0; r < CHUNK; r++) {
            const float w = wsm[TMA_BASE + c * CHUNK + r];
            float4 o;
            o.x = v.x * w; o.y = v.y * w; o.z = v.z * w; o.w = v.w * w;
            buf[cb][r * (D_DIM / 4) + t] = o;
        }
        asm volatile("fence.proxy.async.shared::cta;" ::: "memory");
        __syncthreads();

        if (t == 0) {
            asm volatile(
                "cp.async.bulk.global.shared::cta.bulk_group [%0], [%1], %2;"
                :: "l"(grow + (size_t)(TMA_BASE + c * CHUNK) * D_DIM),
                   "r"(smem_u32(&buf[cb][0])),
                   "n"(CHUNK * D_DIM * 4)
                : "memory");
            asm volatile("cp.async.bulk.commit_group;" ::: "memory");
        }

        // While the TMA engine drains this chunk, push 8 STG rows directly.
        #pragma unroll
        for (int r = 0; r < CHUNK; r++) {
            const int row = c * CHUNK + r;        // rows 0..31 over 4 chunks
            const float w = wsm[row];
            float4 o;
            o.x = v.x * w; o.y = v.y * w; o.z = v.z * w; o.w = v.w * w;
            __stcs(sbase + (size_t)row * (D_DIM / 4), o);
        }
    }

    // Drain TMA before CTA exit.
    if (t == 0)
        asm volatile("cp.async.bulk.wait_group 0;" ::: "memory");
}

extern "C" void kernel_launch(void* const* d_in, const int* in_sizes, int n_in,
                              void* d_out, int out_size) {
    const float* x   = (const float*)d_in[0];   // [4096, 64]
    const float* act = (const float*)d_in[1];   // [4096, 512]
    float* out = (float*)d_out;

    decision_gate_kernel<<<B_DIM, 128>>>(x, act, out);
}